// round 8
// baseline (speedup 1.0000x reference)
#include <cuda_runtime.h>
#include <cuda_bf16.h>
#include <cstdint>

// Problem constants
#define NB   32      // batch
#define NC   8192    // checks
#define NV   16384   // vars
#define NITR 15
#define RCAP 64      // max check degree slots (mean ~16.4), tiers of 16
#define CCAP 40      // max var degree slots (mean ~8.2), tiers of 8

// Scratch (allocation-free: __device__ globals)
// Adjacency lists store PRE-SCALED indices (idx * NB). Dummy = zero row.
// ALL slots are initialized (dummy beyond degree) so loads are branch-free.
__device__ int   g_csr_col[NC * RCAP];
__device__ int   g_csr_cnt[NC];
__device__ int   g_csc_row[NV * CCAP];
__device__ int   g_csc_cnt[NV];
__device__ float g_vbel[(NV + 1) * NB];   // beliefs (v, b); row NV = zeros
__device__ float g_cmsg[(NC + 1) * NB];   // check msgs (c, b); row NC = zeros
__device__ float g_llr_t[NV * NB];        // channel llrs, transposed
__device__ float g_ssign[NC * NB];        // 1 - 2*syndrome, transposed

// ---------------------------------------------------------------------------
__global__ void zero_cnt_kernel() {
    int tid = blockIdx.x * blockDim.x + threadIdx.x;
    if (tid < NC) g_csr_cnt[tid] = 0;
    if (tid < NV) g_csc_cnt[tid] = 0;
    if (tid < NB) {
        g_vbel[NV * NB + tid] = 0.0f;   // dummy var row
        g_cmsg[NC * NB + tid] = 0.0f;   // dummy check row
    }
}

// One warp per H row. Each lane keeps 4 independent uint4 loads in flight.
__global__ void extract_kernel(const uint4* __restrict__ H) {
    int warp = (blockIdx.x * blockDim.x + threadIdx.x) >> 5;
    if (warp >= NC) return;
    int lane = threadIdx.x & 31;
    const uint4* row = H + (size_t)warp * (NV / 4);   // 4096 uint4 per row

    for (int base = lane; base < NV / 4; base += 128) {
        uint4 u0 = row[base];
        uint4 u1 = row[base + 32];
        uint4 u2 = row[base + 64];
        uint4 u3 = row[base + 96];
        #pragma unroll
        for (int g = 0; g < 4; g++) {
            uint4 u = (g == 0) ? u0 : (g == 1) ? u1 : (g == 2) ? u2 : u3;
            if (u.x | u.y | u.z | u.w) {
                int vb = (base + g * 32) * 4;
                #pragma unroll
                for (int j = 0; j < 4; j++) {
                    unsigned val = (j == 0) ? u.x : (j == 1) ? u.y : (j == 2) ? u.z : u.w;
                    if (val) {
                        int v = vb + j;
                        int p = atomicAdd(&g_csr_cnt[warp], 1);
                        if (p < RCAP) g_csr_col[warp * RCAP + p] = v * NB;   // pre-scaled
                        int q = atomicAdd(&g_csc_cnt[v], 1);
                        if (q < CCAP) g_csc_row[v * CCAP + q] = warp * NB;   // pre-scaled
                    }
                }
            }
        }
    }
}

// Merged pad + prep. Pad now fills ALL remaining slots with dummies so the
// phase kernels can load index slots unconditionally (branch-free loads).
#define PADB 64
__global__ void padprep_kernel(const float* __restrict__ syndrome,
                               const float* __restrict__ llr) {
    __shared__ float tile[32][33];
    int bid = blockIdx.x;
    if (bid < PADB) {
        int tid = bid * 256 + threadIdx.x;
        if (tid < NC) {
            int cnt = g_csr_cnt[tid]; if (cnt > RCAP) cnt = RCAP;
            int p = (cnt + 15) & ~15; if (p > RCAP) p = RCAP;
            if (p == 0) p = 16;
            for (int k = cnt; k < RCAP; k++) g_csr_col[tid * RCAP + k] = NV * NB;
            g_csr_cnt[tid] = p;
        }
        if (tid < NV) {
            int cnt = g_csc_cnt[tid]; if (cnt > CCAP) cnt = CCAP;
            int p = (cnt + 7) & ~7;   if (p > CCAP) p = CCAP;
            if (p == 0) p = 8;
            for (int k = cnt; k < CCAP; k++) g_csc_row[tid * CCAP + k] = NC * NB;
            g_csc_cnt[tid] = p;
        }
        return;
    }
    int tx = threadIdx.x & 31, ty = threadIdx.x >> 5;   // ty in 0..7
    int t = bid - PADB;
    if (t < NV / 32) {
        int v0 = t * 32;
        #pragma unroll
        for (int i = 0; i < 32; i += 8)
            tile[ty + i][tx] = llr[(size_t)(ty + i) * NV + v0 + tx];
        __syncthreads();
        #pragma unroll
        for (int i = 0; i < 32; i += 8) {
            float x = tile[tx][ty + i];
            int idx = (v0 + ty + i) * NB + tx;
            g_llr_t[idx] = x;
            g_vbel[idx]  = x;
        }
    } else {
        int c0 = (t - NV / 32) * 32;
        #pragma unroll
        for (int i = 0; i < 32; i += 8)
            tile[ty + i][tx] = syndrome[(size_t)(ty + i) * NC + c0 + tx];
        __syncthreads();
        #pragma unroll
        for (int i = 0; i < 32; i += 8)
            g_ssign[(c0 + ty + i) * NB + tx] = 1.0f - 2.0f * tile[tx][ty + i];
    }
}

// Gather+sum of 16 values from 4 preloaded index packs.
__device__ __forceinline__ float gather16(const int4 q[4],
                                          const float* __restrict__ tbl,
                                          int lane) {
    float x[16];
    #pragma unroll
    for (int i = 0; i < 4; i++) {
        x[4 * i + 0] = tbl[q[i].x + lane];
        x[4 * i + 1] = tbl[q[i].y + lane];
        x[4 * i + 2] = tbl[q[i].z + lane];
        x[4 * i + 3] = tbl[q[i].w + lane];
    }
    float s = 0.0f;
    #pragma unroll
    for (int i = 0; i < 16; i++) s += x[i];
    return s;
}

__device__ __forceinline__ float gather8(const int4 q[2],
                                         const float* __restrict__ tbl,
                                         int lane) {
    float x[8];
    #pragma unroll
    for (int i = 0; i < 2; i++) {
        x[4 * i + 0] = tbl[q[i].x + lane];
        x[4 * i + 1] = tbl[q[i].y + lane];
        x[4 * i + 2] = tbl[q[i].z + lane];
        x[4 * i + 3] = tbl[q[i].w + lane];
    }
    float s = 0.0f;
    #pragma unroll
    for (int i = 0; i < 8; i++) s += x[i];
    return s;
}

// ---------------------------------------------------------------------------
// v -> c : one warp per check. After gridsync: degree + first index batch +
// ssign all issued in parallel (1 RT), then gathers (1 RT). Tier-16 (~52% of
// checks) sees only 2 exposed round trips.
__global__ void __launch_bounds__(256, 8)
check_kernel(const float* __restrict__ w_vc) {
    cudaTriggerProgrammaticLaunchCompletion();
    int c = (blockIdx.x * blockDim.x + threadIdx.x) >> 5;
    int lane = threadIdx.x & 31;
    if (c >= NC) { cudaGridDependencySynchronize(); return; }
    const int4* cols = (const int4*)&g_csr_col[c * RCAP];

    cudaGridDependencySynchronize();

    // Parallel round trip 1: degree, first 16 indices, syndrome sign.
    int degp = g_csr_cnt[c];                       // 16/32/48/64
    int4 q[4];
    q[0] = cols[0]; q[1] = cols[1]; q[2] = cols[2]; q[3] = cols[3];
    float ss = g_ssign[c * NB + lane];

    float sum;
    if (degp == 16) {
        sum = gather16(q, g_vbel, lane);
    } else if (degp == 32) {
        int4 q2[4];
        q2[0] = cols[4]; q2[1] = cols[5]; q2[2] = cols[6]; q2[3] = cols[7];
        sum = gather16(q, g_vbel, lane) + gather16(q2, g_vbel, lane);
    } else {                                        // rare tail (48/64)
        sum = gather16(q, g_vbel, lane);
        for (int k = 16; k < degp; k += 16) {
            int4 t[4];
            t[0] = cols[(k >> 2)];     t[1] = cols[(k >> 2) + 1];
            t[2] = cols[(k >> 2) + 2]; t[3] = cols[(k >> 2) + 3];
            sum += gather16(t, g_vbel, lane);
        }
    }

    float tt = tanhf(0.5f * (*w_vc) * sum);
    g_cmsg[c * NB + lane] = ss * tt;
}

// c -> v + damped update : one warp per var. Same branch-free-load structure.
__global__ void __launch_bounds__(256, 8)
var_kernel(const float* __restrict__ w_cv,
           const float* __restrict__ damping) {
    cudaTriggerProgrammaticLaunchCompletion();
    int v = (blockIdx.x * blockDim.x + threadIdx.x) >> 5;
    int lane = threadIdx.x & 31;
    if (v >= NV) { cudaGridDependencySynchronize(); return; }
    const int4* rows = (const int4*)&g_csc_row[v * CCAP];
    int idx = v * NB + lane;

    cudaGridDependencySynchronize();

    // Parallel round trip 1: degree, first 8 indices, llr, old belief.
    int degp = g_csc_cnt[v];                       // 8/16/24/32/40
    int4 q[2];
    q[0] = rows[0]; q[1] = rows[1];
    float lx  = g_llr_t[idx];
    float old = g_vbel[idx];

    float sum;
    if (degp == 8) {
        sum = gather8(q, g_cmsg, lane);
    } else if (degp == 16) {
        int4 q2[2];
        q2[0] = rows[2]; q2[1] = rows[3];
        sum = gather8(q, g_cmsg, lane) + gather8(q2, g_cmsg, lane);
    } else {                                        // rare tail (24+)
        sum = gather8(q, g_cmsg, lane);
        for (int k = 8; k < degp; k += 8) {
            int4 t[2];
            t[0] = rows[(k >> 2)]; t[1] = rows[(k >> 2) + 1];
            sum += gather8(t, g_cmsg, lane);
        }
    }

    float dmp = *damping;
    g_vbel[idx] = dmp * old + (1.0f - dmp) * (lx + (*w_cv) * sum);
}

// out[b][v] = sigmoid(-belief); smem-tile transpose, coalesced both sides.
__global__ void output_kernel(float* __restrict__ out) {
    __shared__ float tile[32][33];
    cudaGridDependencySynchronize();
    int tx = threadIdx.x & 31, ty = threadIdx.x >> 5;
    int v0 = blockIdx.x * 32;
    #pragma unroll
    for (int i = 0; i < 32; i += 8)
        tile[ty + i][tx] = g_vbel[(v0 + ty + i) * NB + tx];
    __syncthreads();
    #pragma unroll
    for (int i = 0; i < 32; i += 8) {
        float x = tile[tx][ty + i];
        out[(size_t)(ty + i) * NV + v0 + tx] = 1.0f / (1.0f + expf(x));
    }
}

// ---------------------------------------------------------------------------
template <typename... Args>
static void launch_pdl(void (*kern)(Args...), int grid, int block, Args... args) {
    cudaLaunchConfig_t cfg = {};
    cfg.gridDim  = dim3(grid, 1, 1);
    cfg.blockDim = dim3(block, 1, 1);
    cfg.stream   = 0;
    cudaLaunchAttribute attr[1];
    attr[0].id = cudaLaunchAttributeProgrammaticStreamSerialization;
    attr[0].val.programmaticStreamSerializationAllowed = 1;
    cfg.attrs = attr;
    cfg.numAttrs = 1;
    cudaLaunchKernelEx(&cfg, kern, args...);
}

extern "C" void kernel_launch(void* const* d_in, const int* in_sizes, int n_in,
                              void* d_out, int out_size) {
    const float* syndrome = (const float*)d_in[0];   // (32, 8192)
    const uint4* parity   = (const uint4*)d_in[1];   // (8192, 16384) fp32 as bits
    const float* llr      = (const float*)d_in[2];   // (32, 16384)
    const float* w_vc     = (const float*)d_in[3];
    const float* w_cv     = (const float*)d_in[4];
    const float* damping  = (const float*)d_in[5];
    float* out = (float*)d_out;

    zero_cnt_kernel<<<(NV + 255) / 256, 256>>>();
    extract_kernel<<<(NC * 32 + 255) / 256, 256>>>(parity);
    padprep_kernel<<<PADB + NV / 32 + NC / 32, 256>>>(syndrome, llr);

    for (int it = 0; it < NITR; it++) {
        launch_pdl(check_kernel, (NC * 32 + 255) / 256, 256, w_vc);
        launch_pdl(var_kernel,   (NV * 32 + 255) / 256, 256, w_cv, damping);
    }

    launch_pdl(output_kernel, NV / 32, 256, out);
}

// round 9
// speedup vs baseline: 1.3343x; 1.3343x over previous
#include <cuda_runtime.h>
#include <cuda_bf16.h>
#include <cstdint>

// Problem constants
#define NB   32      // batch
#define NC   8192    // checks
#define NV   16384   // vars
#define NITR 15
#define RCAP 64      // max check degree slots (mean ~16.4), tiers of 16
#define CCAP 40      // max var degree slots (mean ~8.2), tiers of 8

// Scratch (allocation-free: __device__ globals)
// Adjacency lists store PRE-SCALED indices (idx * NB). Dummy = zero row.
__device__ int   g_csr_col[NC * RCAP];
__device__ int   g_csr_cnt[NC];
__device__ int   g_csc_row[NV * CCAP];
__device__ int   g_csc_cnt[NV];
__device__ float g_vbel[(NV + 1) * NB];   // beliefs (v, b); row NV = zeros
__device__ float g_cmsg[(NC + 1) * NB];   // check msgs (c, b); row NC = zeros
__device__ float g_llr_t[NV * NB];        // channel llrs, transposed
__device__ float g_ssign[NC * NB];        // 1 - 2*syndrome, transposed

// ---------------------------------------------------------------------------
__global__ void zero_cnt_kernel() {
    int tid = blockIdx.x * blockDim.x + threadIdx.x;
    if (tid < NC) g_csr_cnt[tid] = 0;
    if (tid < NV) g_csc_cnt[tid] = 0;
    if (tid < NB) {
        g_vbel[NV * NB + tid] = 0.0f;   // dummy var row
        g_cmsg[NC * NB + tid] = 0.0f;   // dummy check row
    }
}

// One warp per H row. Each lane keeps 8 independent uint4 loads in flight
// (128 B/lane/step). Triggers PDL completion at entry so padprep's
// independent transpose blocks overlap the whole scan.
__global__ void extract_kernel(const uint4* __restrict__ H) {
    cudaTriggerProgrammaticLaunchCompletion();
    int warp = (blockIdx.x * blockDim.x + threadIdx.x) >> 5;
    if (warp >= NC) return;
    int lane = threadIdx.x & 31;
    const uint4* row = H + (size_t)warp * (NV / 4);   // 4096 uint4 per row

    for (int base = lane; base < NV / 4; base += 256) {
        uint4 u[8];
        #pragma unroll
        for (int g = 0; g < 8; g++) u[g] = row[base + g * 32];
        #pragma unroll
        for (int g = 0; g < 8; g++) {
            if (u[g].x | u[g].y | u[g].z | u[g].w) {
                int vb = (base + g * 32) * 4;
                #pragma unroll
                for (int j = 0; j < 4; j++) {
                    unsigned val = (j == 0) ? u[g].x : (j == 1) ? u[g].y
                                 : (j == 2) ? u[g].z : u[g].w;
                    if (val) {
                        int v = vb + j;
                        int p = atomicAdd(&g_csr_cnt[warp], 1);
                        if (p < RCAP) g_csr_col[warp * RCAP + p] = v * NB;   // pre-scaled
                        int q = atomicAdd(&g_csc_cnt[v], 1);
                        if (q < CCAP) g_csc_row[v * CCAP + q] = warp * NB;   // pre-scaled
                    }
                }
            }
        }
    }
}

// Merged pad + prep. Launched with PDL after extract:
//  - transpose blocks (independent of extract) run concurrently with it
//  - pad blocks gridsync first (need final counts)
#define PADB 64
__global__ void padprep_kernel(const float* __restrict__ syndrome,
                               const float* __restrict__ llr) {
    __shared__ float tile[32][33];
    int bid = blockIdx.x;
    if (bid < PADB) {
        cudaGridDependencySynchronize();           // wait: extract done
        int tid = bid * 256 + threadIdx.x;
        if (tid < NC) {
            int cnt = g_csr_cnt[tid]; if (cnt > RCAP) cnt = RCAP;
            int p = (cnt + 15) & ~15; if (p > RCAP) p = RCAP;
            if (p == 0) p = 16;
            for (int k = cnt; k < p; k++) g_csr_col[tid * RCAP + k] = NV * NB;
            g_csr_cnt[tid] = p;
        }
        if (tid < NV) {
            int cnt = g_csc_cnt[tid]; if (cnt > CCAP) cnt = CCAP;
            int p = (cnt + 7) & ~7;   if (p > CCAP) p = CCAP;
            if (p == 0) p = 8;
            for (int k = cnt; k < p; k++) g_csc_row[tid * CCAP + k] = NC * NB;
            g_csc_cnt[tid] = p;
        }
        return;
    }
    // Transpose blocks: no dependency on extract — overlap it.
    int tx = threadIdx.x & 31, ty = threadIdx.x >> 5;   // ty in 0..7
    int t = bid - PADB;
    if (t < NV / 32) {
        int v0 = t * 32;
        #pragma unroll
        for (int i = 0; i < 32; i += 8)
            tile[ty + i][tx] = llr[(size_t)(ty + i) * NV + v0 + tx];
        __syncthreads();
        #pragma unroll
        for (int i = 0; i < 32; i += 8) {
            float x = tile[tx][ty + i];
            int idx = (v0 + ty + i) * NB + tx;
            g_llr_t[idx] = x;
            g_vbel[idx]  = x;
        }
    } else {
        int c0 = (t - NV / 32) * 32;
        #pragma unroll
        for (int i = 0; i < 32; i += 8)
            tile[ty + i][tx] = syndrome[(size_t)(ty + i) * NC + c0 + tx];
        __syncthreads();
        #pragma unroll
        for (int i = 0; i < 32; i += 8)
            g_ssign[(c0 + ty + i) * NB + tx] = 1.0f - 2.0f * tile[tx][ty + i];
    }
}

__device__ __forceinline__ float fast_tanh(float x) {
    float y;
    asm("tanh.approx.f32 %0, %1;" : "=f"(y) : "f"(x));
    return y;
}

// Straight-line gather+sum over N4*4 indices loaded inline.
template <int N4>
__device__ __forceinline__ float gather_sum(const int4* __restrict__ p,
                                            const float* __restrict__ tbl,
                                            int lane) {
    int4 q[N4];
    #pragma unroll
    for (int i = 0; i < N4; i++) q[i] = p[i];
    float x[N4 * 4];
    #pragma unroll
    for (int i = 0; i < N4; i++) {
        x[4 * i + 0] = tbl[q[i].x + lane];
        x[4 * i + 1] = tbl[q[i].y + lane];
        x[4 * i + 2] = tbl[q[i].z + lane];
        x[4 * i + 3] = tbl[q[i].w + lane];
    }
    float s = 0.0f;
    #pragma unroll
    for (int i = 0; i < N4 * 4; i++) s += x[i];
    return s;
}

// ---------------------------------------------------------------------------
// v -> c : one warp per check. PDL: trigger early; cheap topology prelude
// (degree + base pointer only — anything more spills at the 32-reg cap);
// gridsync before touching vbel/ssign.
__global__ void __launch_bounds__(256, 8)
check_kernel(const float* __restrict__ w_vc) {
    cudaTriggerProgrammaticLaunchCompletion();
    int c = (blockIdx.x * blockDim.x + threadIdx.x) >> 5;
    int lane = threadIdx.x & 31;
    if (c >= NC) { cudaGridDependencySynchronize(); return; }

    // --- cheap prelude: degree + base pointer only ---
    int degp = g_csr_cnt[c];                       // 16/32/48/64
    const int4* cols = (const int4*)&g_csr_col[c * RCAP];

    cudaGridDependencySynchronize();               // wait: predecessor's data

    float sum;
    if (degp == 16)      sum = gather_sum<4>(cols, g_vbel, lane);
    else if (degp == 32) sum = gather_sum<8>(cols, g_vbel, lane);
    else {                                          // rare tail (48/64)
        sum = 0.0f;
        for (int k = 0; k < degp; k += 16)
            sum += gather_sum<4>(cols + (k >> 2), g_vbel, lane);
    }

    float tt = fast_tanh(0.5f * (*w_vc) * sum);
    g_cmsg[c * NB + lane] = g_ssign[c * NB + lane] * tt;
}

// c -> v + damped update : one warp per var. Same structure.
__global__ void __launch_bounds__(256, 8)
var_kernel(const float* __restrict__ w_cv,
           const float* __restrict__ damping) {
    cudaTriggerProgrammaticLaunchCompletion();
    int v = (blockIdx.x * blockDim.x + threadIdx.x) >> 5;
    int lane = threadIdx.x & 31;
    if (v >= NV) { cudaGridDependencySynchronize(); return; }

    // --- cheap prelude ---
    int degp = g_csc_cnt[v];                       // 8/16/24/32/40
    const int4* rows = (const int4*)&g_csc_row[v * CCAP];

    cudaGridDependencySynchronize();               // wait: check phase done

    float sum;
    if (degp == 8)       sum = gather_sum<2>(rows, g_cmsg, lane);
    else if (degp == 16) sum = gather_sum<4>(rows, g_cmsg, lane);
    else {                                          // rare tail (24+)
        sum = 0.0f;
        for (int k = 0; k < degp; k += 8)
            sum += gather_sum<2>(rows + (k >> 2), g_cmsg, lane);
    }

    float dmp = *damping;
    int idx = v * NB + lane;
    float old = g_vbel[idx];
    g_vbel[idx] = dmp * old + (1.0f - dmp) * (g_llr_t[idx] + (*w_cv) * sum);
}

// out[b][v] = sigmoid(-belief); smem-tile transpose, coalesced both sides.
__global__ void output_kernel(float* __restrict__ out) {
    __shared__ float tile[32][33];
    cudaGridDependencySynchronize();
    int tx = threadIdx.x & 31, ty = threadIdx.x >> 5;
    int v0 = blockIdx.x * 32;
    #pragma unroll
    for (int i = 0; i < 32; i += 8)
        tile[ty + i][tx] = g_vbel[(v0 + ty + i) * NB + tx];
    __syncthreads();
    #pragma unroll
    for (int i = 0; i < 32; i += 8) {
        float x = tile[tx][ty + i];
        out[(size_t)(ty + i) * NV + v0 + tx] = 1.0f / (1.0f + expf(x));
    }
}

// ---------------------------------------------------------------------------
template <typename... Args>
static void launch_pdl(void (*kern)(Args...), int grid, int block, Args... args) {
    cudaLaunchConfig_t cfg = {};
    cfg.gridDim  = dim3(grid, 1, 1);
    cfg.blockDim = dim3(block, 1, 1);
    cfg.stream   = 0;
    cudaLaunchAttribute attr[1];
    attr[0].id = cudaLaunchAttributeProgrammaticStreamSerialization;
    attr[0].val.programmaticStreamSerializationAllowed = 1;
    cfg.attrs = attr;
    cfg.numAttrs = 1;
    cudaLaunchKernelEx(&cfg, kern, args...);
}

extern "C" void kernel_launch(void* const* d_in, const int* in_sizes, int n_in,
                              void* d_out, int out_size) {
    const float* syndrome = (const float*)d_in[0];   // (32, 8192)
    const uint4* parity   = (const uint4*)d_in[1];   // (8192, 16384) fp32 as bits
    const float* llr      = (const float*)d_in[2];   // (32, 16384)
    const float* w_vc     = (const float*)d_in[3];
    const float* w_cv     = (const float*)d_in[4];
    const float* damping  = (const float*)d_in[5];
    float* out = (float*)d_out;

    zero_cnt_kernel<<<(NV + 255) / 256, 256>>>();
    extract_kernel<<<(NC * 32 + 255) / 256, 256>>>(parity);
    // PDL: transpose blocks overlap extract; pad blocks gridsync inside.
    launch_pdl(padprep_kernel, PADB + NV / 32 + NC / 32, 256, syndrome, llr);

    for (int it = 0; it < NITR; it++) {
        launch_pdl(check_kernel, (NC * 32 + 255) / 256, 256, w_vc);
        launch_pdl(var_kernel,   (NV * 32 + 255) / 256, 256, w_cv, damping);
    }

    launch_pdl(output_kernel, NV / 32, 256, out);
}

// round 10
// speedup vs baseline: 1.4050x; 1.0530x over previous
#include <cuda_runtime.h>
#include <cuda_bf16.h>
#include <cstdint>

// Problem constants
#define NB   32      // batch
#define NC   8192    // checks
#define NV   16384   // vars
#define NITR 15
#define RCAP 64      // max check degree slots (mean ~16.4), tiers of 16
#define CCAP 40      // max var degree slots (mean ~8.2), tiers of 8

// Scratch (allocation-free: __device__ globals)
// Adjacency lists store PRE-SCALED indices (idx * NB). Dummy = zero row.
__device__ int   g_csr_col[NC * RCAP];
__device__ int   g_csr_cnt[NC];
__device__ int   g_csc_row[NV * CCAP];
__device__ int   g_csc_cnt[NV];
__device__ float g_vbel[(NV + 1) * NB];   // beliefs (v, b); row NV = zeros
__device__ float g_cmsg[(NC + 1) * NB];   // check msgs (c, b); row NC = zeros
__device__ float g_llr_t[NV * NB];        // channel llrs, transposed
__device__ float g_ssign[NC * NB];        // 1 - 2*syndrome, transposed

// ---------------------------------------------------------------------------
__global__ void zero_cnt_kernel() {
    int tid = blockIdx.x * blockDim.x + threadIdx.x;
    if (tid < NC) g_csr_cnt[tid] = 0;
    if (tid < NV) g_csc_cnt[tid] = 0;
    if (tid < NB) {
        g_vbel[NV * NB + tid] = 0.0f;   // dummy var row
        g_cmsg[NC * NB + tid] = 0.0f;   // dummy check row
    }
}

// One warp per H row. Each lane keeps 4 independent uint4 loads in flight.
__global__ void extract_kernel(const uint4* __restrict__ H) {
    int warp = (blockIdx.x * blockDim.x + threadIdx.x) >> 5;
    if (warp >= NC) return;
    int lane = threadIdx.x & 31;
    const uint4* row = H + (size_t)warp * (NV / 4);   // 4096 uint4 per row

    for (int base = lane; base < NV / 4; base += 128) {
        uint4 u0 = row[base];
        uint4 u1 = row[base + 32];
        uint4 u2 = row[base + 64];
        uint4 u3 = row[base + 96];
        #pragma unroll
        for (int g = 0; g < 4; g++) {
            uint4 u = (g == 0) ? u0 : (g == 1) ? u1 : (g == 2) ? u2 : u3;
            if (u.x | u.y | u.z | u.w) {
                int vb = (base + g * 32) * 4;
                #pragma unroll
                for (int j = 0; j < 4; j++) {
                    unsigned val = (j == 0) ? u.x : (j == 1) ? u.y : (j == 2) ? u.z : u.w;
                    if (val) {
                        int v = vb + j;
                        int p = atomicAdd(&g_csr_cnt[warp], 1);
                        if (p < RCAP) g_csr_col[warp * RCAP + p] = v * NB;   // pre-scaled
                        int q = atomicAdd(&g_csc_cnt[v], 1);
                        if (q < CCAP) g_csc_row[v * CCAP + q] = warp * NB;   // pre-scaled
                    }
                }
            }
        }
    }
}

// Merged pad + prep.
#define PADB 64
__global__ void padprep_kernel(const float* __restrict__ syndrome,
                               const float* __restrict__ llr) {
    __shared__ float tile[32][33];
    int bid = blockIdx.x;
    if (bid < PADB) {
        int tid = bid * 256 + threadIdx.x;
        if (tid < NC) {
            int cnt = g_csr_cnt[tid]; if (cnt > RCAP) cnt = RCAP;
            int p = (cnt + 15) & ~15; if (p > RCAP) p = RCAP;
            if (p == 0) p = 16;
            for (int k = cnt; k < p; k++) g_csr_col[tid * RCAP + k] = NV * NB;
            g_csr_cnt[tid] = p;
        }
        if (tid < NV) {
            int cnt = g_csc_cnt[tid]; if (cnt > CCAP) cnt = CCAP;
            int p = (cnt + 7) & ~7;   if (p > CCAP) p = CCAP;
            if (p == 0) p = 8;
            for (int k = cnt; k < p; k++) g_csc_row[tid * CCAP + k] = NC * NB;
            g_csc_cnt[tid] = p;
        }
        return;
    }
    int tx = threadIdx.x & 31, ty = threadIdx.x >> 5;   // ty in 0..7
    int t = bid - PADB;
    if (t < NV / 32) {
        int v0 = t * 32;
        #pragma unroll
        for (int i = 0; i < 32; i += 8)
            tile[ty + i][tx] = llr[(size_t)(ty + i) * NV + v0 + tx];
        __syncthreads();
        #pragma unroll
        for (int i = 0; i < 32; i += 8) {
            float x = tile[tx][ty + i];
            int idx = (v0 + ty + i) * NB + tx;
            g_llr_t[idx] = x;
            g_vbel[idx]  = x;
        }
    } else {
        int c0 = (t - NV / 32) * 32;
        #pragma unroll
        for (int i = 0; i < 32; i += 8)
            tile[ty + i][tx] = syndrome[(size_t)(ty + i) * NC + c0 + tx];
        __syncthreads();
        #pragma unroll
        for (int i = 0; i < 32; i += 8)
            g_ssign[(c0 + ty + i) * NB + tx] = 1.0f - 2.0f * tile[tx][ty + i];
    }
}

__device__ __forceinline__ float fast_tanh(float x) {
    float y;
    asm("tanh.approx.f32 %0, %1;" : "=f"(y) : "f"(x));
    return y;
}

// Straight-line gather+sum over N4*4 indices loaded inline.
template <int N4>
__device__ __forceinline__ float gather_sum(const int4* __restrict__ p,
                                            const float* __restrict__ tbl,
                                            int lane) {
    int4 q[N4];
    #pragma unroll
    for (int i = 0; i < N4; i++) q[i] = p[i];
    float x[N4 * 4];
    #pragma unroll
    for (int i = 0; i < N4; i++) {
        x[4 * i + 0] = tbl[q[i].x + lane];
        x[4 * i + 1] = tbl[q[i].y + lane];
        x[4 * i + 2] = tbl[q[i].z + lane];
        x[4 * i + 3] = tbl[q[i].w + lane];
    }
    float s = 0.0f;
    #pragma unroll
    for (int i = 0; i < N4 * 4; i++) s += x[i];
    return s;
}

// ---------------------------------------------------------------------------
// v -> c : one warp per check. PDL: trigger early; cheap topology prelude;
// gridsync before touching vbel/ssign. Single wave (1024 CTAs at occ 8).
__global__ void __launch_bounds__(256, 8)
check_kernel(const float* __restrict__ w_vc) {
    cudaTriggerProgrammaticLaunchCompletion();
    int c = (blockIdx.x * blockDim.x + threadIdx.x) >> 5;
    int lane = threadIdx.x & 31;
    if (c >= NC) { cudaGridDependencySynchronize(); return; }

    // --- cheap prelude: degree + base pointer only ---
    int degp = g_csr_cnt[c];                       // 16/32/48/64
    const int4* cols = (const int4*)&g_csr_col[c * RCAP];

    cudaGridDependencySynchronize();               // wait: predecessor's data

    float sum;
    if (degp == 16)      sum = gather_sum<4>(cols, g_vbel, lane);
    else if (degp == 32) sum = gather_sum<8>(cols, g_vbel, lane);
    else {                                          // rare tail (48/64)
        sum = 0.0f;
        for (int k = 0; k < degp; k += 16)
            sum += gather_sum<4>(cols + (k >> 2), g_vbel, lane);
    }

    float tt = fast_tanh(0.5f * (*w_vc) * sum);
    g_cmsg[c * NB + lane] = g_ssign[c * NB + lane] * tt;
}

// c -> v + damped update : TWO vars per warp -> 8192 warps total = single
// wave (vs 16384 warps = 2 waves before), and two independent gather chains
// per warp double the exposed MLP.
__global__ void __launch_bounds__(256, 8)
var_kernel(const float* __restrict__ w_cv,
           const float* __restrict__ damping) {
    cudaTriggerProgrammaticLaunchCompletion();
    int gw = (blockIdx.x * blockDim.x + threadIdx.x) >> 5;
    int lane = threadIdx.x & 31;
    int v0 = gw * 2;
    if (v0 >= NV) { cudaGridDependencySynchronize(); return; }
    int v1 = v0 + 1;

    // --- cheap prelude ---
    int deg0 = g_csc_cnt[v0];
    int deg1 = g_csc_cnt[v1];
    const int4* rows0 = (const int4*)&g_csc_row[v0 * CCAP];
    const int4* rows1 = (const int4*)&g_csc_row[v1 * CCAP];

    cudaGridDependencySynchronize();               // wait: check phase done

    float sum0, sum1;
    if (deg0 == 8)       sum0 = gather_sum<2>(rows0, g_cmsg, lane);
    else if (deg0 == 16) sum0 = gather_sum<4>(rows0, g_cmsg, lane);
    else {
        sum0 = 0.0f;
        for (int k = 0; k < deg0; k += 8)
            sum0 += gather_sum<2>(rows0 + (k >> 2), g_cmsg, lane);
    }
    if (deg1 == 8)       sum1 = gather_sum<2>(rows1, g_cmsg, lane);
    else if (deg1 == 16) sum1 = gather_sum<4>(rows1, g_cmsg, lane);
    else {
        sum1 = 0.0f;
        for (int k = 0; k < deg1; k += 8)
            sum1 += gather_sum<2>(rows1 + (k >> 2), g_cmsg, lane);
    }

    float dmp = *damping;
    float wc  = *w_cv;
    int idx0 = v0 * NB + lane;
    int idx1 = v1 * NB + lane;
    float old0 = g_vbel[idx0];
    float old1 = g_vbel[idx1];
    g_vbel[idx0] = dmp * old0 + (1.0f - dmp) * (g_llr_t[idx0] + wc * sum0);
    g_vbel[idx1] = dmp * old1 + (1.0f - dmp) * (g_llr_t[idx1] + wc * sum1);
}

// out[b][v] = sigmoid(-belief); smem-tile transpose, coalesced both sides.
__global__ void output_kernel(float* __restrict__ out) {
    __shared__ float tile[32][33];
    cudaGridDependencySynchronize();
    int tx = threadIdx.x & 31, ty = threadIdx.x >> 5;
    int v0 = blockIdx.x * 32;
    #pragma unroll
    for (int i = 0; i < 32; i += 8)
        tile[ty + i][tx] = g_vbel[(v0 + ty + i) * NB + tx];
    __syncthreads();
    #pragma unroll
    for (int i = 0; i < 32; i += 8) {
        float x = tile[tx][ty + i];
        out[(size_t)(ty + i) * NV + v0 + tx] = 1.0f / (1.0f + expf(x));
    }
}

// ---------------------------------------------------------------------------
template <typename... Args>
static void launch_pdl(void (*kern)(Args...), int grid, int block, Args... args) {
    cudaLaunchConfig_t cfg = {};
    cfg.gridDim  = dim3(grid, 1, 1);
    cfg.blockDim = dim3(block, 1, 1);
    cfg.stream   = 0;
    cudaLaunchAttribute attr[1];
    attr[0].id = cudaLaunchAttributeProgrammaticStreamSerialization;
    attr[0].val.programmaticStreamSerializationAllowed = 1;
    cfg.attrs = attr;
    cfg.numAttrs = 1;
    cudaLaunchKernelEx(&cfg, kern, args...);
}

extern "C" void kernel_launch(void* const* d_in, const int* in_sizes, int n_in,
                              void* d_out, int out_size) {
    const float* syndrome = (const float*)d_in[0];   // (32, 8192)
    const uint4* parity   = (const uint4*)d_in[1];   // (8192, 16384) fp32 as bits
    const float* llr      = (const float*)d_in[2];   // (32, 16384)
    const float* w_vc     = (const float*)d_in[3];
    const float* w_cv     = (const float*)d_in[4];
    const float* damping  = (const float*)d_in[5];
    float* out = (float*)d_out;

    zero_cnt_kernel<<<(NV + 255) / 256, 256>>>();
    extract_kernel<<<(NC * 32 + 255) / 256, 256>>>(parity);
    padprep_kernel<<<PADB + NV / 32 + NC / 32, 256>>>(syndrome, llr);

    for (int it = 0; it < NITR; it++) {
        launch_pdl(check_kernel, (NC * 32 + 255) / 256, 256, w_vc);
        launch_pdl(var_kernel,   (NV * 16 + 255) / 256, 256, w_cv, damping);
    }

    launch_pdl(output_kernel, NV / 32, 256, out);
}